// round 13
// baseline (speedup 1.0000x reference)
#include <cuda_runtime.h>
#include <cuda_bf16.h>
#include <cstdint>

#define BATCH 8
#define HIMG 80
#define WIMG 80
#define CDIM 768
#define NPOS (HIMG * WIMG)        // 6400
#define CQKV (3 * CDIM)           // 2304
#define WIN 14
#define NWIN 6
#define NHEAD 12
#define HD 64
#define NWP (WIN * WIN)           // 196
#define MROWS (BATCH * NPOS)      // 51200

// ---------------- scratch (__device__ globals: allocation-free rule) -------
__device__ float g_qkv[(size_t)MROWS * CQKV];
__device__ __nv_bfloat16 g_ahi[(size_t)MROWS * CDIM];
__device__ __nv_bfloat16 g_alo[(size_t)MROWS * CDIM];
__device__ __nv_bfloat16 g_bhi[(size_t)CQKV * CDIM];
__device__ __nv_bfloat16 g_blo[(size_t)CQKV * CDIM];

// ---------------- PTX helpers (no 'a'-suffix features) ---------------------
__device__ __forceinline__ uint32_t smem_u32(const void* p) {
    uint32_t a;
    asm("{ .reg .u64 t; cvta.to.shared.u64 t, %1; cvt.u32.u64 %0, t; }"
        : "=r"(a) : "l"(p));
    return a;
}
__device__ __forceinline__ void cp_async16(uint32_t dst, const void* src) {
    asm volatile("cp.async.cg.shared.global [%0], [%1], 16;"
                 :: "r"(dst), "l"(src));
}
#define CP_COMMIT() asm volatile("cp.async.commit_group;" ::: "memory")
#define CP_WAIT(n)  asm volatile("cp.async.wait_group %0;" :: "n"(n) : "memory")

__device__ __forceinline__ void ldm_x4(uint32_t* r, uint32_t addr) {
    asm volatile("ldmatrix.sync.aligned.m8n8.x4.shared.b16 {%0,%1,%2,%3}, [%4];"
                 : "=r"(r[0]), "=r"(r[1]), "=r"(r[2]), "=r"(r[3]) : "r"(addr));
}
__device__ __forceinline__ void mma_bf16(float* d, const uint32_t* a,
                                         uint32_t b0, uint32_t b1) {
    asm volatile(
        "mma.sync.aligned.m16n8k16.row.col.f32.bf16.bf16.f32 "
        "{%0,%1,%2,%3}, {%4,%5,%6,%7}, {%8,%9}, {%0,%1,%2,%3};"
        : "+f"(d[0]), "+f"(d[1]), "+f"(d[2]), "+f"(d[3])
        : "r"(a[0]), "r"(a[1]), "r"(a[2]), "r"(a[3]), "r"(b0), "r"(b1));
}

// ---------------------------------------------------------------------------
// bf16x3 GEMM via mma.sync (R8 measured-best configuration, unchanged).
// ---------------------------------------------------------------------------
#define BM 128
#define BN 128
#define BK 32
#define STAGES 3
#define TILE_B (BM * BK * 2)          // 8192
#define STAGE_B (4 * TILE_B)          // 32768
#define GEMM_SMEM (STAGES * STAGE_B)  // 98304

__global__ __launch_bounds__(256, 2) void gemm_mma_bf16x3(
    const __nv_bfloat16* __restrict__ Ah, const __nv_bfloat16* __restrict__ Al,
    const __nv_bfloat16* __restrict__ Bh, const __nv_bfloat16* __restrict__ Bl,
    const float* __restrict__ bias, float* __restrict__ C,
    int M, int N, int K)
{
    extern __shared__ char sm[];
    const uint32_t smb = smem_u32(sm);
    const int tid  = threadIdx.x;
    const int wid  = tid >> 5;
    const int lane = tid & 31;
    const int bm = blockIdx.y * BM;
    const int bn = blockIdx.x * BN;
    const int warp_m = (wid >> 2) * 64;
    const int warp_n = (wid & 3) * 32;

    const __nv_bfloat16* gA[2] = { Ah + (size_t)bm * K, Al + (size_t)bm * K };
    const __nv_bfloat16* gB[2] = { Bh + (size_t)bn * K, Bl + (size_t)bn * K };

    float acc[4][4][4];
#pragma unroll
    for (int i = 0; i < 4; i++)
#pragma unroll
        for (int j = 0; j < 4; j++)
#pragma unroll
            for (int k = 0; k < 4; k++) acc[i][j][k] = 0.f;

    const int nchunk = K / BK;

    auto load_chunk = [&](int c) {
        const uint32_t bufb = smb + (c % STAGES) * STAGE_B;
        const int k0 = c * BK;
#pragma unroll
        for (int t = 0; t < 4; t++) {
            const __nv_bfloat16* src = (t < 2 ? gA[t] : gB[t - 2]) + k0;
            const uint32_t dstb = bufb + t * TILE_B;
#pragma unroll
            for (int i = 0; i < 2; i++) {
                const int idx = i * 256 + tid;
                const int row = idx >> 2, cc = idx & 3;
                const uint32_t sw = row * 64 + ((cc ^ ((row >> 1) & 3)) << 4);
                cp_async16(dstb + sw, src + (size_t)row * K + cc * 8);
            }
        }
        CP_COMMIT();
    };

    load_chunk(0);
    load_chunk(1);

    const int lrow  = lane & 15;
    const int lhalf = lane >> 4;

    for (int c = 0; c < nchunk; c++) {
        if (c + 1 < nchunk) CP_WAIT(1);
        else                CP_WAIT(0);
        __syncthreads();
        if (c + 2 < nchunk) load_chunk(c + 2);

        const uint32_t aHb = smb + (c % STAGES) * STAGE_B;
        const uint32_t aLb = aHb + TILE_B;
        const uint32_t bHb = aHb + 2 * TILE_B;
        const uint32_t bLb = aHb + 3 * TILE_B;

#pragma unroll
        for (int ks = 0; ks < 2; ks++) {
            const int ccol = ks * 2 + lhalf;
            uint32_t bh[2][4], bl[2][4];
#pragma unroll
            for (int j = 0; j < 2; j++) {
                const int row = warp_n + j * 16 + lrow;
                const uint32_t off = row * 64 + ((ccol ^ ((row >> 1) & 3)) << 4);
                ldm_x4(bh[j], bHb + off);
                ldm_x4(bl[j], bLb + off);
            }
#pragma unroll
            for (int mi = 0; mi < 4; mi++) {
                const int row = warp_m + mi * 16 + lrow;
                const uint32_t off = row * 64 + ((ccol ^ ((row >> 1) & 3)) << 4);
                uint32_t ah[4], al[4];
                ldm_x4(ah, aHb + off);
                ldm_x4(al, aLb + off);
#pragma unroll
                for (int nj = 0; nj < 4; nj++) {
                    const int p = nj >> 1, s = nj & 1;
                    mma_bf16(acc[mi][nj], ah, bh[p][s], bh[p][s + 2]);
                    mma_bf16(acc[mi][nj], ah, bl[p][s], bl[p][s + 2]);
                    mma_bf16(acc[mi][nj], al, bh[p][s], bh[p][s + 2]);
                }
            }
        }
        __syncthreads();
    }

    const int row_t = lane >> 2;
    const int col_t = (lane & 3) * 2;
#pragma unroll
    for (int mi = 0; mi < 4; mi++) {
#pragma unroll
        for (int r = 0; r < 2; r++) {
            const int row = bm + warp_m + mi * 16 + row_t + r * 8;
            float* crow = C + (size_t)row * N + bn;
#pragma unroll
            for (int nj = 0; nj < 4; nj++) {
                const int col = warp_n + nj * 8 + col_t;
                float2 v;
                v.x = acc[mi][nj][r * 2 + 0];
                v.y = acc[mi][nj][r * 2 + 1];
                if (bias) { v.x += bias[bn + col]; v.y += bias[bn + col + 1]; }
                *(float2*)(crow + col) = v;
            }
        }
    }
}

// ---------------------------------------------------------------------------
// fp32 -> bf16 hi/lo splits
// ---------------------------------------------------------------------------
__global__ __launch_bounds__(256) void split_rm(
    const float* __restrict__ in, __nv_bfloat16* __restrict__ hi,
    __nv_bfloat16* __restrict__ lo, int n4)
{
    int i = blockIdx.x * blockDim.x + threadIdx.x;
    if (i < n4) {
        float4 v = ((const float4*)in)[i];
        float f[4] = { v.x, v.y, v.z, v.w };
        __nv_bfloat16 h[4], l[4];
#pragma unroll
        for (int j = 0; j < 4; j++) {
            h[j] = __float2bfloat16_rn(f[j]);
            l[j] = __float2bfloat16_rn(f[j] - __bfloat162float(h[j]));
        }
        ((ushort4*)hi)[i] = make_ushort4(
            __bfloat16_as_ushort(h[0]), __bfloat16_as_ushort(h[1]),
            __bfloat16_as_ushort(h[2]), __bfloat16_as_ushort(h[3]));
        ((ushort4*)lo)[i] = make_ushort4(
            __bfloat16_as_ushort(l[0]), __bfloat16_as_ushort(l[1]),
            __bfloat16_as_ushort(l[2]), __bfloat16_as_ushort(l[3]));
    }
}

__global__ __launch_bounds__(256) void split_tr(
    const float* __restrict__ W, __nv_bfloat16* __restrict__ hi,
    __nv_bfloat16* __restrict__ lo, int K, int N)
{
    int idx = blockIdx.x * blockDim.x + threadIdx.x;
    if (idx < K * N) {
        int n = idx / K, k = idx % K;
        float v = W[(size_t)k * N + n];
        __nv_bfloat16 h = __float2bfloat16_rn(v);
        hi[idx] = h;
        lo[idx] = __float2bfloat16_rn(v - __bfloat162float(h));
    }
}

// ---------------------------------------------------------------------------
// Windowed attention: 2 query rows per thread, 16 dims per thread.
// quad = tid&3 owns dims [quad*16,+16); pair = tid>>2 owns rows {pair, pair+104}.
// K/V quad loaded ONCE per key serves BOTH rows -> block LDS wavefronts halve.
// Writes bf16 hi/lo output directly (feeds GEMM3).
// ---------------------------------------------------------------------------
#define ATTN_THREADS 416

__global__ __launch_bounds__(ATTN_THREADS) void win_attn(
    const float* __restrict__ qkv,
    __nv_bfloat16* __restrict__ ohi, __nv_bfloat16* __restrict__ olo)
{
    const int idx  = blockIdx.x;
    const int head = idx % NHEAD;
    const int l    = (idx / NHEAD) % (NWIN * NWIN);
    const int b    = idx / (NHEAD * NWIN * NWIN);
    const int wi = l / NWIN, wj = l % NWIN;

    extern __shared__ float smf[];
    float* Ks = smf;               // [196][64]
    float* Vs = smf + NWP * HD;

    const int tid = threadIdx.x;

    for (int i = tid; i < NWP * (HD / 4); i += ATTN_THREADS) {
        const int p = i / (HD / 4);
        const int f = i % (HD / 4);
        const int r = p / WIN, c = p % WIN;
        const int h = wi * WIN + r, w = wj * WIN + c;
        float4 kv = make_float4(0.f, 0.f, 0.f, 0.f);
        float4 vv = make_float4(0.f, 0.f, 0.f, 0.f);
        if (h < HIMG && w < WIMG) {
            const size_t base =
                (size_t)(b * NPOS + h * WIMG + w) * CQKV + head * HD + f * 4;
            kv = *(const float4*)(qkv + base + CDIM);
            vv = *(const float4*)(qkv + base + 2 * CDIM);
        }
        ((float4*)Ks)[i] = kv;
        ((float4*)Vs)[i] = vv;
    }
    __syncthreads();

    const int quad = tid & 3;               // dims [quad*16, +16)
    const int pair = tid >> 2;              // 0..103
    const int row0 = pair;                  // 0..103  (always < NWP)
    const int row1 = pair + 104;            // 104..207 (>=NWP for pair>=92)

    // row -> (h,w) and validity
    const int r0 = row0 / WIN, c0 = row0 % WIN;
    const int h0 = wi * WIN + r0, w0 = wj * WIN + c0;
    const bool v0 = (h0 < HIMG) && (w0 < WIMG);
    const int r1c = (row1 < NWP ? row1 : NWP - 1);
    const int r1 = r1c / WIN, c1 = r1c % WIN;
    const int h1 = wi * WIN + r1, w1 = wj * WIN + c1;
    const bool v1 = (row1 < NWP) && (h1 < HIMG) && (w1 < WIMG);
    const int h0c = h0 < HIMG ? h0 : HIMG - 1;
    const int w0c = w0 < WIMG ? w0 : WIMG - 1;
    const int h1c = h1 < HIMG ? h1 : HIMG - 1;
    const int w1c = w1 < WIMG ? w1 : WIMG - 1;

    const size_t q0base =
        (size_t)(b * NPOS + h0c * WIMG + w0c) * CQKV + head * HD + quad * 16;
    const size_t q1base =
        (size_t)(b * NPOS + h1c * WIMG + w1c) * CQKV + head * HD + quad * 16;
    float4 q0[4], q1[4];
#pragma unroll
    for (int d = 0; d < 4; d++) {
        q0[d] = *(const float4*)(qkv + q0base + d * 4);
        q1[d] = *(const float4*)(qkv + q1base + d * 4);
    }

    float m0 = -1e30f, l0 = 0.f, m1 = -1e30f, l1 = 0.f;
    float acc0[16], acc1[16];
#pragma unroll
    for (int d = 0; d < 16; d++) { acc0[d] = 0.f; acc1[d] = 0.f; }

    for (int j = 0; j < NWP; j++) {
        const float4* kj = (const float4*)(Ks + j * HD + quad * 16);
        float4 k0v = kj[0], k1v = kj[1], k2v = kj[2], k3v = kj[3];

        // two independent dots on the SAME loaded K quad
        float a0 = q0[0].x * k0v.x, b0 = q1[0].x * k0v.x;
        a0 = fmaf(q0[0].y, k0v.y, a0); b0 = fmaf(q1[0].y, k0v.y, b0);
        a0 = fmaf(q0[0].z, k0v.z, a0); b0 = fmaf(q1[0].z, k0v.z, b0);
        a0 = fmaf(q0[0].w, k0v.w, a0); b0 = fmaf(q1[0].w, k0v.w, b0);
        float a1 = q0[1].x * k1v.x, b1 = q1[1].x * k1v.x;
        a1 = fmaf(q0[1].y, k1v.y, a1); b1 = fmaf(q1[1].y, k1v.y, b1);
        a1 = fmaf(q0[1].z, k1v.z, a1); b1 = fmaf(q1[1].z, k1v.z, b1);
        a1 = fmaf(q0[1].w, k1v.w, a1); b1 = fmaf(q1[1].w, k1v.w, b1);
        float a2 = q0[2].x * k2v.x, b2 = q1[2].x * k2v.x;
        a2 = fmaf(q0[2].y, k2v.y, a2); b2 = fmaf(q1[2].y, k2v.y, b2);
        a2 = fmaf(q0[2].z, k2v.z, a2); b2 = fmaf(q1[2].z, k2v.z, b2);
        a2 = fmaf(q0[2].w, k2v.w, a2); b2 = fmaf(q1[2].w, k2v.w, b2);
        float a3 = q0[3].x * k3v.x, b3 = q1[3].x * k3v.x;
        a3 = fmaf(q0[3].y, k3v.y, a3); b3 = fmaf(q1[3].y, k3v.y, b3);
        a3 = fmaf(q0[3].z, k3v.z, a3); b3 = fmaf(q1[3].z, k3v.z, b3);
        a3 = fmaf(q0[3].w, k3v.w, a3); b3 = fmaf(q1[3].w, k3v.w, b3);

        float sa = (a0 + a1) + (a2 + a3);
        float sb = (b0 + b1) + (b2 + b3);
        // reduce across the 4 lanes of the quad group
        sa += __shfl_xor_sync(0xffffffffu, sa, 1);
        sa += __shfl_xor_sync(0xffffffffu, sa, 2);
        sb += __shfl_xor_sync(0xffffffffu, sb, 1);
        sb += __shfl_xor_sync(0xffffffffu, sb, 2);
        const float s0 = sa * 0.125f;
        const float s1 = sb * 0.125f;

        if (s0 > m0) {
            const float corr = __expf(m0 - s0);
            l0 *= corr;
#pragma unroll
            for (int d = 0; d < 16; d++) acc0[d] *= corr;
            m0 = s0;
        }
        if (s1 > m1) {
            const float corr = __expf(m1 - s1);
            l1 *= corr;
#pragma unroll
            for (int d = 0; d < 16; d++) acc1[d] *= corr;
            m1 = s1;
        }
        const float p0 = __expf(s0 - m0);
        const float p1 = __expf(s1 - m1);
        l0 += p0;
        l1 += p1;

        const float4* vj = (const float4*)(Vs + j * HD + quad * 16);
#pragma unroll
        for (int d = 0; d < 4; d++) {
            float4 vv = vj[d];
            acc0[d * 4 + 0] = fmaf(p0, vv.x, acc0[d * 4 + 0]);
            acc0[d * 4 + 1] = fmaf(p0, vv.y, acc0[d * 4 + 1]);
            acc0[d * 4 + 2] = fmaf(p0, vv.z, acc0[d * 4 + 2]);
            acc0[d * 4 + 3] = fmaf(p0, vv.w, acc0[d * 4 + 3]);
            acc1[d * 4 + 0] = fmaf(p1, vv.x, acc1[d * 4 + 0]);
            acc1[d * 4 + 1] = fmaf(p1, vv.y, acc1[d * 4 + 1]);
            acc1[d * 4 + 2] = fmaf(p1, vv.z, acc1[d * 4 + 2]);
            acc1[d * 4 + 3] = fmaf(p1, vv.w, acc1[d * 4 + 3]);
        }
    }

    if (v0) {
        const float inv = 1.f / l0;
        const size_t obase =
            (size_t)(b * NPOS + h0 * WIMG + w0) * CDIM + head * HD + quad * 16;
        ushort hi16[16], lo16[16];
#pragma unroll
        for (int d = 0; d < 16; d++) {
            const float v = acc0[d] * inv;
            const __nv_bfloat16 hh = __float2bfloat16_rn(v);
            hi16[d] = __bfloat16_as_ushort(hh);
            lo16[d] = __bfloat16_as_ushort(
                __float2bfloat16_rn(v - __bfloat162float(hh)));
        }
        *(uint4*)(ohi + obase)     = ((const uint4*)hi16)[0];
        *(uint4*)(ohi + obase + 8) = ((const uint4*)hi16)[1];
        *(uint4*)(olo + obase)     = ((const uint4*)lo16)[0];
        *(uint4*)(olo + obase + 8) = ((const uint4*)lo16)[1];
    }
    if (v1) {
        const float inv = 1.f / l1;
        const size_t obase =
            (size_t)(b * NPOS + h1 * WIMG + w1) * CDIM + head * HD + quad * 16;
        ushort hi16[16], lo16[16];
#pragma unroll
        for (int d = 0; d < 16; d++) {
            const float v = acc1[d] * inv;
            const __nv_bfloat16 hh = __float2bfloat16_rn(v);
            hi16[d] = __bfloat16_as_ushort(hh);
            lo16[d] = __bfloat16_as_ushort(
                __float2bfloat16_rn(v - __bfloat162float(hh)));
        }
        *(uint4*)(ohi + obase)     = ((const uint4*)hi16)[0];
        *(uint4*)(ohi + obase + 8) = ((const uint4*)hi16)[1];
        *(uint4*)(olo + obase)     = ((const uint4*)lo16)[0];
        *(uint4*)(olo + obase + 8) = ((const uint4*)lo16)[1];
    }
}

// ---------------------------------------------------------------------------
extern "C" void kernel_launch(void* const* d_in, const int* in_sizes, int n_in,
                              void* d_out, int out_size)
{
    const float* x     = (const float*)d_in[0];
    const float* Wqkv  = (const float*)d_in[1];
    const float* Wproj = (const float*)d_in[2];
    const float* bproj = (const float*)d_in[3];
    float* out = (float*)d_out;

    float *qkv;
    __nv_bfloat16 *ahi, *alo, *bhi, *blo;
    cudaGetSymbolAddress((void**)&qkv, g_qkv);
    cudaGetSymbolAddress((void**)&ahi, g_ahi);
    cudaGetSymbolAddress((void**)&alo, g_alo);
    cudaGetSymbolAddress((void**)&bhi, g_bhi);
    cudaGetSymbolAddress((void**)&blo, g_blo);

    cudaFuncSetAttribute(gemm_mma_bf16x3,
                         cudaFuncAttributeMaxDynamicSharedMemorySize, GEMM_SMEM);
    const int attn_smem = 2 * NWP * HD * (int)sizeof(float);
    cudaFuncSetAttribute(win_attn,
                         cudaFuncAttributeMaxDynamicSharedMemorySize, attn_smem);

    const int M = MROWS;

    // ---- GEMM1: qkv = x @ Wqkv ----
    {
        int n4 = M * CDIM / 4;
        split_rm<<<(n4 + 255) / 256, 256>>>(x, ahi, alo, n4);
        int ne = CDIM * CQKV;
        split_tr<<<(ne + 255) / 256, 256>>>(Wqkv, bhi, blo, CDIM, CQKV);
        dim3 grid(CQKV / BN, M / BM);
        gemm_mma_bf16x3<<<grid, 256, GEMM_SMEM>>>(
            ahi, alo, bhi, blo, nullptr, qkv, M, CQKV, CDIM);
    }

    // ---- windowed attention (writes bf16 hi/lo directly) ----
    {
        dim3 grid(BATCH * NWIN * NWIN * NHEAD);
        win_attn<<<grid, ATTN_THREADS, attn_smem>>>(qkv, ahi, alo);
    }

    // ---- GEMM3: out = att @ Wproj + bproj ----
    {
        int ne = CDIM * CDIM;
        split_tr<<<(ne + 255) / 256, 256>>>(Wproj, bhi, blo, CDIM, CDIM);
        dim3 grid(CDIM / BN, M / BM);
        gemm_mma_bf16x3<<<grid, 256, GEMM_SMEM>>>(
            ahi, alo, bhi, blo, bproj, out, M, CDIM, CDIM);
    }
}

// round 14
// speedup vs baseline: 1.0077x; 1.0077x over previous
#include <cuda_runtime.h>
#include <cuda_bf16.h>
#include <cstdint>

#define BATCH 8
#define HIMG 80
#define WIMG 80
#define CDIM 768
#define NPOS (HIMG * WIMG)        // 6400
#define CQKV (3 * CDIM)           // 2304
#define WIN 14
#define NWIN 6
#define NHEAD 12
#define HD 64
#define NWP (WIN * WIN)           // 196
#define MROWS (BATCH * NPOS)      // 51200

// ---------------- scratch (__device__ globals: allocation-free rule) -------
__device__ float g_qkv[(size_t)MROWS * CQKV];
__device__ __nv_bfloat16 g_ahi[(size_t)MROWS * CDIM];
__device__ __nv_bfloat16 g_alo[(size_t)MROWS * CDIM];
__device__ __nv_bfloat16 g_bhi[(size_t)CQKV * CDIM];
__device__ __nv_bfloat16 g_blo[(size_t)CQKV * CDIM];

// ---------------- PTX helpers (no 'a'-suffix features) ---------------------
__device__ __forceinline__ uint32_t smem_u32(const void* p) {
    uint32_t a;
    asm("{ .reg .u64 t; cvta.to.shared.u64 t, %1; cvt.u32.u64 %0, t; }"
        : "=r"(a) : "l"(p));
    return a;
}
__device__ __forceinline__ void cp_async16(uint32_t dst, const void* src) {
    asm volatile("cp.async.cg.shared.global [%0], [%1], 16;"
                 :: "r"(dst), "l"(src));
}
#define CP_COMMIT() asm volatile("cp.async.commit_group;" ::: "memory")
#define CP_WAIT(n)  asm volatile("cp.async.wait_group %0;" :: "n"(n) : "memory")

__device__ __forceinline__ void ldm_x4(uint32_t* r, uint32_t addr) {
    asm volatile("ldmatrix.sync.aligned.m8n8.x4.shared.b16 {%0,%1,%2,%3}, [%4];"
                 : "=r"(r[0]), "=r"(r[1]), "=r"(r[2]), "=r"(r[3]) : "r"(addr));
}
__device__ __forceinline__ void mma_bf16(float* d, const uint32_t* a,
                                         uint32_t b0, uint32_t b1) {
    asm volatile(
        "mma.sync.aligned.m16n8k16.row.col.f32.bf16.bf16.f32 "
        "{%0,%1,%2,%3}, {%4,%5,%6,%7}, {%8,%9}, {%0,%1,%2,%3};"
        : "+f"(d[0]), "+f"(d[1]), "+f"(d[2]), "+f"(d[3])
        : "r"(a[0]), "r"(a[1]), "r"(a[2]), "r"(a[3]), "r"(b0), "r"(b1));
}

// ---------------------------------------------------------------------------
// bf16x3 GEMM via mma.sync (R8 measured-best config; loads issued before wait).
// ---------------------------------------------------------------------------
#define BM 128
#define BN 128
#define BK 32
#define STAGES 3
#define TILE_B (BM * BK * 2)          // 8192
#define STAGE_B (4 * TILE_B)          // 32768
#define GEMM_SMEM (STAGES * STAGE_B)  // 98304

__global__ __launch_bounds__(256, 2) void gemm_mma_bf16x3(
    const __nv_bfloat16* __restrict__ Ah, const __nv_bfloat16* __restrict__ Al,
    const __nv_bfloat16* __restrict__ Bh, const __nv_bfloat16* __restrict__ Bl,
    const float* __restrict__ bias, float* __restrict__ C,
    int M, int N, int K)
{
    extern __shared__ char sm[];
    const uint32_t smb = smem_u32(sm);
    const int tid  = threadIdx.x;
    const int wid  = tid >> 5;
    const int lane = tid & 31;
    const int bm = blockIdx.y * BM;
    const int bn = blockIdx.x * BN;
    const int warp_m = (wid >> 2) * 64;
    const int warp_n = (wid & 3) * 32;

    const __nv_bfloat16* gA[2] = { Ah + (size_t)bm * K, Al + (size_t)bm * K };
    const __nv_bfloat16* gB[2] = { Bh + (size_t)bn * K, Bl + (size_t)bn * K };

    float acc[4][4][4];
#pragma unroll
    for (int i = 0; i < 4; i++)
#pragma unroll
        for (int j = 0; j < 4; j++)
#pragma unroll
            for (int k = 0; k < 4; k++) acc[i][j][k] = 0.f;

    const int nchunk = K / BK;

    auto load_chunk = [&](int c) {
        const uint32_t bufb = smb + (c % STAGES) * STAGE_B;
        const int k0 = c * BK;
#pragma unroll
        for (int t = 0; t < 4; t++) {
            const __nv_bfloat16* src = (t < 2 ? gA[t] : gB[t - 2]) + k0;
            const uint32_t dstb = bufb + t * TILE_B;
#pragma unroll
            for (int i = 0; i < 2; i++) {
                const int idx = i * 256 + tid;
                const int row = idx >> 2, cc = idx & 3;
                const uint32_t sw = row * 64 + ((cc ^ ((row >> 1) & 3)) << 4);
                cp_async16(dstb + sw, src + (size_t)row * K + cc * 8);
            }
        }
        CP_COMMIT();
    };

    load_chunk(0);
    load_chunk(1);

    const int lrow  = lane & 15;
    const int lhalf = lane >> 4;

    for (int c = 0; c < nchunk; c++) {
        // issue the prefetch FIRST (its target buffer was released one full
        // iteration ago by the trailing __syncthreads), then wait for chunk c
        if (c + 2 < nchunk) { load_chunk(c + 2); CP_WAIT(2); }
        else if (c + 1 < nchunk) CP_WAIT(1);
        else                     CP_WAIT(0);
        __syncthreads();

        const uint32_t aHb = smb + (c % STAGES) * STAGE_B;
        const uint32_t aLb = aHb + TILE_B;
        const uint32_t bHb = aHb + 2 * TILE_B;
        const uint32_t bLb = aHb + 3 * TILE_B;

#pragma unroll
        for (int ks = 0; ks < 2; ks++) {
            const int ccol = ks * 2 + lhalf;
            uint32_t bh[2][4], bl[2][4];
#pragma unroll
            for (int j = 0; j < 2; j++) {
                const int row = warp_n + j * 16 + lrow;
                const uint32_t off = row * 64 + ((ccol ^ ((row >> 1) & 3)) << 4);
                ldm_x4(bh[j], bHb + off);
                ldm_x4(bl[j], bLb + off);
            }
#pragma unroll
            for (int mi = 0; mi < 4; mi++) {
                const int row = warp_m + mi * 16 + lrow;
                const uint32_t off = row * 64 + ((ccol ^ ((row >> 1) & 3)) << 4);
                uint32_t ah[4], al[4];
                ldm_x4(ah, aHb + off);
                ldm_x4(al, aLb + off);
#pragma unroll
                for (int nj = 0; nj < 4; nj++) {
                    const int p = nj >> 1, s = nj & 1;
                    mma_bf16(acc[mi][nj], ah, bh[p][s], bh[p][s + 2]);
                    mma_bf16(acc[mi][nj], ah, bl[p][s], bl[p][s + 2]);
                    mma_bf16(acc[mi][nj], al, bh[p][s], bh[p][s + 2]);
                }
            }
        }
        __syncthreads();
    }

    const int row_t = lane >> 2;
    const int col_t = (lane & 3) * 2;
#pragma unroll
    for (int mi = 0; mi < 4; mi++) {
#pragma unroll
        for (int r = 0; r < 2; r++) {
            const int row = bm + warp_m + mi * 16 + row_t + r * 8;
            float* crow = C + (size_t)row * N + bn;
#pragma unroll
            for (int nj = 0; nj < 4; nj++) {
                const int col = warp_n + nj * 8 + col_t;
                float2 v;
                v.x = acc[mi][nj][r * 2 + 0];
                v.y = acc[mi][nj][r * 2 + 1];
                if (bias) { v.x += bias[bn + col]; v.y += bias[bn + col + 1]; }
                *(float2*)(crow + col) = v;
            }
        }
    }
}

// ---------------------------------------------------------------------------
// fp32 -> bf16 hi/lo splits
// ---------------------------------------------------------------------------
__global__ __launch_bounds__(256) void split_rm(
    const float* __restrict__ in, __nv_bfloat16* __restrict__ hi,
    __nv_bfloat16* __restrict__ lo, int n4)
{
    int i = blockIdx.x * blockDim.x + threadIdx.x;
    if (i < n4) {
        float4 v = ((const float4*)in)[i];
        float f[4] = { v.x, v.y, v.z, v.w };
        __nv_bfloat16 h[4], l[4];
#pragma unroll
        for (int j = 0; j < 4; j++) {
            h[j] = __float2bfloat16_rn(f[j]);
            l[j] = __float2bfloat16_rn(f[j] - __bfloat162float(h[j]));
        }
        ((ushort4*)hi)[i] = make_ushort4(
            __bfloat16_as_ushort(h[0]), __bfloat16_as_ushort(h[1]),
            __bfloat16_as_ushort(h[2]), __bfloat16_as_ushort(h[3]));
        ((ushort4*)lo)[i] = make_ushort4(
            __bfloat16_as_ushort(l[0]), __bfloat16_as_ushort(l[1]),
            __bfloat16_as_ushort(l[2]), __bfloat16_as_ushort(l[3]));
    }
}

__global__ __launch_bounds__(256) void split_tr(
    const float* __restrict__ W, __nv_bfloat16* __restrict__ hi,
    __nv_bfloat16* __restrict__ lo, int K, int N)
{
    int idx = blockIdx.x * blockDim.x + threadIdx.x;
    if (idx < K * N) {
        int n = idx / K, k = idx % K;
        float v = W[(size_t)k * N + n];
        __nv_bfloat16 h = __float2bfloat16_rn(v);
        hi[idx] = h;
        lo[idx] = __float2bfloat16_rn(v - __bfloat162float(h));
    }
}

// ---------------------------------------------------------------------------
// Windowed attention, NO online softmax: scores are bounded (|s| <~ 10), so
// plain exp(s) accumulation is exact-safe in fp32 and removes the max-tracking
// branch, conditional rescale, and the serial dependency on m.
// Layout: 2 query rows per thread (rows {pair, pair+104}), 16 dims per thread.
// Writes bf16 hi/lo output directly (feeds GEMM3).
// ---------------------------------------------------------------------------
#define ATTN_THREADS 416

__global__ __launch_bounds__(ATTN_THREADS) void win_attn(
    const float* __restrict__ qkv,
    __nv_bfloat16* __restrict__ ohi, __nv_bfloat16* __restrict__ olo)
{
    const int idx  = blockIdx.x;
    const int head = idx % NHEAD;
    const int l    = (idx / NHEAD) % (NWIN * NWIN);
    const int b    = idx / (NHEAD * NWIN * NWIN);
    const int wi = l / NWIN, wj = l % NWIN;

    extern __shared__ float smf[];
    float* Ks = smf;               // [196][64]
    float* Vs = smf + NWP * HD;

    const int tid = threadIdx.x;

    for (int i = tid; i < NWP * (HD / 4); i += ATTN_THREADS) {
        const int p = i / (HD / 4);
        const int f = i % (HD / 4);
        const int r = p / WIN, c = p % WIN;
        const int h = wi * WIN + r, w = wj * WIN + c;
        float4 kv = make_float4(0.f, 0.f, 0.f, 0.f);
        float4 vv = make_float4(0.f, 0.f, 0.f, 0.f);
        if (h < HIMG && w < WIMG) {
            const size_t base =
                (size_t)(b * NPOS + h * WIMG + w) * CQKV + head * HD + f * 4;
            kv = *(const float4*)(qkv + base + CDIM);
            vv = *(const float4*)(qkv + base + 2 * CDIM);
        }
        ((float4*)Ks)[i] = kv;
        ((float4*)Vs)[i] = vv;
    }
    __syncthreads();

    const int quad = tid & 3;               // dims [quad*16, +16)
    const int pair = tid >> 2;              // 0..103
    const int row0 = pair;
    const int row1 = pair + 104;

    const int r0 = row0 / WIN, c0 = row0 % WIN;
    const int h0 = wi * WIN + r0, w0 = wj * WIN + c0;
    const bool v0 = (h0 < HIMG) && (w0 < WIMG);
    const int r1c = (row1 < NWP ? row1 : NWP - 1);
    const int r1 = r1c / WIN, c1 = r1c % WIN;
    const int h1 = wi * WIN + r1, w1 = wj * WIN + c1;
    const bool v1 = (row1 < NWP) && (h1 < HIMG) && (w1 < WIMG);
    const int h0c = h0 < HIMG ? h0 : HIMG - 1;
    const int w0c = w0 < WIMG ? w0 : WIMG - 1;
    const int h1c = h1 < HIMG ? h1 : HIMG - 1;
    const int w1c = w1 < WIMG ? w1 : WIMG - 1;

    const size_t q0base =
        (size_t)(b * NPOS + h0c * WIMG + w0c) * CQKV + head * HD + quad * 16;
    const size_t q1base =
        (size_t)(b * NPOS + h1c * WIMG + w1c) * CQKV + head * HD + quad * 16;
    float4 q0[4], q1[4];
#pragma unroll
    for (int d = 0; d < 4; d++) {
        q0[d] = *(const float4*)(qkv + q0base + d * 4);
        q1[d] = *(const float4*)(qkv + q1base + d * 4);
    }

    float l0 = 0.f, l1 = 0.f;
    float acc0[16], acc1[16];
#pragma unroll
    for (int d = 0; d < 16; d++) { acc0[d] = 0.f; acc1[d] = 0.f; }

    for (int j = 0; j < NWP; j++) {
        const float4* kj = (const float4*)(Ks + j * HD + quad * 16);
        float4 k0v = kj[0], k1v = kj[1], k2v = kj[2], k3v = kj[3];

        float a0 = q0[0].x * k0v.x, b0 = q1[0].x * k0v.x;
        a0 = fmaf(q0[0].y, k0v.y, a0); b0 = fmaf(q1[0].y, k0v.y, b0);
        a0 = fmaf(q0[0].z, k0v.z, a0); b0 = fmaf(q1[0].z, k0v.z, b0);
        a0 = fmaf(q0[0].w, k0v.w, a0); b0 = fmaf(q1[0].w, k0v.w, b0);
        float a1 = q0[1].x * k1v.x, b1 = q1[1].x * k1v.x;
        a1 = fmaf(q0[1].y, k1v.y, a1); b1 = fmaf(q1[1].y, k1v.y, b1);
        a1 = fmaf(q0[1].z, k1v.z, a1); b1 = fmaf(q1[1].z, k1v.z, b1);
        a1 = fmaf(q0[1].w, k1v.w, a1); b1 = fmaf(q1[1].w, k1v.w, b1);
        float a2 = q0[2].x * k2v.x, b2 = q1[2].x * k2v.x;
        a2 = fmaf(q0[2].y, k2v.y, a2); b2 = fmaf(q1[2].y, k2v.y, b2);
        a2 = fmaf(q0[2].z, k2v.z, a2); b2 = fmaf(q1[2].z, k2v.z, b2);
        a2 = fmaf(q0[2].w, k2v.w, a2); b2 = fmaf(q1[2].w, k2v.w, b2);
        float a3 = q0[3].x * k3v.x, b3 = q1[3].x * k3v.x;
        a3 = fmaf(q0[3].y, k3v.y, a3); b3 = fmaf(q1[3].y, k3v.y, b3);
        a3 = fmaf(q0[3].z, k3v.z, a3); b3 = fmaf(q1[3].z, k3v.z, b3);
        a3 = fmaf(q0[3].w, k3v.w, a3); b3 = fmaf(q1[3].w, k3v.w, b3);

        float sa = (a0 + a1) + (a2 + a3);
        float sb = (b0 + b1) + (b2 + b3);
        sa += __shfl_xor_sync(0xffffffffu, sa, 1);
        sa += __shfl_xor_sync(0xffffffffu, sa, 2);
        sb += __shfl_xor_sync(0xffffffffu, sb, 1);
        sb += __shfl_xor_sync(0xffffffffu, sb, 2);

        const float p0 = __expf(sa * 0.125f);
        const float p1 = __expf(sb * 0.125f);
        l0 += p0;
        l1 += p1;

        const float4* vj = (const float4*)(Vs + j * HD + quad * 16);
#pragma unroll
        for (int d = 0; d < 4; d++) {
            float4 vv = vj[d];
            acc0[d * 4 + 0] = fmaf(p0, vv.x, acc0[d * 4 + 0]);
            acc0[d * 4 + 1] = fmaf(p0, vv.y, acc0[d * 4 + 1]);
            acc0[d * 4 + 2] = fmaf(p0, vv.z, acc0[d * 4 + 2]);
            acc0[d * 4 + 3] = fmaf(p0, vv.w, acc0[d * 4 + 3]);
            acc1[d * 4 + 0] = fmaf(p1, vv.x, acc1[d * 4 + 0]);
            acc1[d * 4 + 1] = fmaf(p1, vv.y, acc1[d * 4 + 1]);
            acc1[d * 4 + 2] = fmaf(p1, vv.z, acc1[d * 4 + 2]);
            acc1[d * 4 + 3] = fmaf(p1, vv.w, acc1[d * 4 + 3]);
        }
    }

    if (v0) {
        const float inv = 1.f / l0;
        const size_t obase =
            (size_t)(b * NPOS + h0 * WIMG + w0) * CDIM + head * HD + quad * 16;
        ushort hi16[16], lo16[16];
#pragma unroll
        for (int d = 0; d < 16; d++) {
            const float v = acc0[d] * inv;
            const __nv_bfloat16 hh = __float2bfloat16_rn(v);
            hi16[d] = __bfloat16_as_ushort(hh);
            lo16[d] = __bfloat16_as_ushort(
                __float2bfloat16_rn(v - __bfloat162float(hh)));
        }
        *(uint4*)(ohi + obase)     = ((const uint4*)hi16)[0];
        *(uint4*)(ohi + obase + 8) = ((const uint4*)hi16)[1];
        *(uint4*)(olo + obase)     = ((const uint4*)lo16)[0];
        *(uint4*)(olo + obase + 8) = ((const uint4*)lo16)[1];
    }
    if (v1) {
        const float inv = 1.f / l1;
        const size_t obase =
            (size_t)(b * NPOS + h1 * WIMG + w1) * CDIM + head * HD + quad * 16;
        ushort hi16[16], lo16[16];
#pragma unroll
        for (int d = 0; d < 16; d++) {
            const float v = acc1[d] * inv;
            const __nv_bfloat16 hh = __float2bfloat16_rn(v);
            hi16[d] = __bfloat16_as_ushort(hh);
            lo16[d] = __bfloat16_as_ushort(
                __float2bfloat16_rn(v - __bfloat162float(hh)));
        }
        *(uint4*)(ohi + obase)     = ((const uint4*)hi16)[0];
        *(uint4*)(ohi + obase + 8) = ((const uint4*)hi16)[1];
        *(uint4*)(olo + obase)     = ((const uint4*)lo16)[0];
        *(uint4*)(olo + obase + 8) = ((const uint4*)lo16)[1];
    }
}

// ---------------------------------------------------------------------------
extern "C" void kernel_launch(void* const* d_in, const int* in_sizes, int n_in,
                              void* d_out, int out_size)
{
    const float* x     = (const float*)d_in[0];
    const float* Wqkv  = (const float*)d_in[1];
    const float* Wproj = (const float*)d_in[2];
    const float* bproj = (const float*)d_in[3];
    float* out = (float*)d_out;

    float *qkv;
    __nv_bfloat16 *ahi, *alo, *bhi, *blo;
    cudaGetSymbolAddress((void**)&qkv, g_qkv);
    cudaGetSymbolAddress((void**)&ahi, g_ahi);
    cudaGetSymbolAddress((void**)&alo, g_alo);
    cudaGetSymbolAddress((void**)&bhi, g_bhi);
    cudaGetSymbolAddress((void**)&blo, g_blo);

    cudaFuncSetAttribute(gemm_mma_bf16x3,
                         cudaFuncAttributeMaxDynamicSharedMemorySize, GEMM_SMEM);
    const int attn_smem = 2 * NWP * HD * (int)sizeof(float);
    cudaFuncSetAttribute(win_attn,
                         cudaFuncAttributeMaxDynamicSharedMemorySize, attn_smem);

    const int M = MROWS;

    // ---- GEMM1: qkv = x @ Wqkv ----
    {
        int n4 = M * CDIM / 4;
        split_rm<<<(n4 + 255) / 256, 256>>>(x, ahi, alo, n4);
        int ne = CDIM * CQKV;
        split_tr<<<(ne + 255) / 256, 256>>>(Wqkv, bhi, blo, CDIM, CQKV);
        dim3 grid(CQKV / BN, M / BM);
        gemm_mma_bf16x3<<<grid, 256, GEMM_SMEM>>>(
            ahi, alo, bhi, blo, nullptr, qkv, M, CQKV, CDIM);
    }

    // ---- windowed attention (writes bf16 hi/lo directly) ----
    {
        dim3 grid(BATCH * NWIN * NWIN * NHEAD);
        win_attn<<<grid, ATTN_THREADS, attn_smem>>>(qkv, ahi, alo);
    }

    // ---- GEMM3: out = att @ Wproj + bproj ----
    {
        int ne = CDIM * CDIM;
        split_tr<<<(ne + 255) / 256, 256>>>(Wproj, bhi, blo, CDIM, CDIM);
        dim3 grid(CDIM / BN, M / BM);
        gemm_mma_bf16x3<<<grid, 256, GEMM_SMEM>>>(
            ahi, alo, bhi, blo, bproj, out, M, CDIM, CDIM);
    }
}

// round 15
// speedup vs baseline: 1.6304x; 1.6179x over previous
#include <cuda_runtime.h>
#include <cuda_bf16.h>
#include <cstdint>

#define BATCH 8
#define HIMG 80
#define WIMG 80
#define CDIM 768
#define NPOS (HIMG * WIMG)        // 6400
#define CQKV (3 * CDIM)           // 2304
#define WIN 14
#define NWIN 6
#define NHEAD 12
#define HD 64
#define NWP (WIN * WIN)           // 196
#define MROWS (BATCH * NPOS)      // 51200

// ---------------- scratch (__device__ globals: allocation-free rule) -------
__device__ float g_qkv[(size_t)MROWS * CQKV];
__device__ __nv_bfloat16 g_ahi[(size_t)MROWS * CDIM];
__device__ __nv_bfloat16 g_alo[(size_t)MROWS * CDIM];
__device__ __nv_bfloat16 g_bhi[(size_t)CQKV * CDIM];
__device__ __nv_bfloat16 g_blo[(size_t)CQKV * CDIM];

// ---------------- PTX helpers (no 'a'-suffix features) ---------------------
__device__ __forceinline__ uint32_t smem_u32(const void* p) {
    uint32_t a;
    asm("{ .reg .u64 t; cvta.to.shared.u64 t, %1; cvt.u32.u64 %0, t; }"
        : "=r"(a) : "l"(p));
    return a;
}
__device__ __forceinline__ void cp_async16(uint32_t dst, const void* src) {
    asm volatile("cp.async.cg.shared.global [%0], [%1], 16;"
                 :: "r"(dst), "l"(src));
}
#define CP_COMMIT() asm volatile("cp.async.commit_group;" ::: "memory")
#define CP_WAIT(n)  asm volatile("cp.async.wait_group %0;" :: "n"(n) : "memory")

__device__ __forceinline__ void ldm_x4(uint32_t* r, uint32_t addr) {
    asm volatile("ldmatrix.sync.aligned.m8n8.x4.shared.b16 {%0,%1,%2,%3}, [%4];"
                 : "=r"(r[0]), "=r"(r[1]), "=r"(r[2]), "=r"(r[3]) : "r"(addr));
}
__device__ __forceinline__ void ldm_x4_trans(uint32_t* r, uint32_t addr) {
    asm volatile("ldmatrix.sync.aligned.m8n8.x4.trans.shared.b16 {%0,%1,%2,%3}, [%4];"
                 : "=r"(r[0]), "=r"(r[1]), "=r"(r[2]), "=r"(r[3]) : "r"(addr));
}
__device__ __forceinline__ void mma_bf16(float* d, const uint32_t* a,
                                         uint32_t b0, uint32_t b1) {
    asm volatile(
        "mma.sync.aligned.m16n8k16.row.col.f32.bf16.bf16.f32 "
        "{%0,%1,%2,%3}, {%4,%5,%6,%7}, {%8,%9}, {%0,%1,%2,%3};"
        : "+f"(d[0]), "+f"(d[1]), "+f"(d[2]), "+f"(d[3])
        : "r"(a[0]), "r"(a[1]), "r"(a[2]), "r"(a[3]), "r"(b0), "r"(b1));
}
// split two fp32 into packed bf16 hi and lo pairs
__device__ __forceinline__ void split2(float x, float y,
                                       uint32_t& hp, uint32_t& lp) {
    __nv_bfloat16 hx = __float2bfloat16_rn(x);
    __nv_bfloat16 hy = __float2bfloat16_rn(y);
    __nv_bfloat16 lx = __float2bfloat16_rn(x - __bfloat162float(hx));
    __nv_bfloat16 ly = __float2bfloat16_rn(y - __bfloat162float(hy));
    hp = (uint32_t)__bfloat16_as_ushort(hx) |
         ((uint32_t)__bfloat16_as_ushort(hy) << 16);
    lp = (uint32_t)__bfloat16_as_ushort(lx) |
         ((uint32_t)__bfloat16_as_ushort(ly) << 16);
}

// ---------------------------------------------------------------------------
// bf16x3 GEMM via mma.sync (R8 measured-best config; unchanged).
// ---------------------------------------------------------------------------
#define BM 128
#define BN 128
#define BK 32
#define STAGES 3
#define TILE_B (BM * BK * 2)          // 8192
#define STAGE_B (4 * TILE_B)          // 32768
#define GEMM_SMEM (STAGES * STAGE_B)  // 98304

__global__ __launch_bounds__(256, 2) void gemm_mma_bf16x3(
    const __nv_bfloat16* __restrict__ Ah, const __nv_bfloat16* __restrict__ Al,
    const __nv_bfloat16* __restrict__ Bh, const __nv_bfloat16* __restrict__ Bl,
    const float* __restrict__ bias, float* __restrict__ C,
    int M, int N, int K)
{
    extern __shared__ char sm[];
    const uint32_t smb = smem_u32(sm);
    const int tid  = threadIdx.x;
    const int wid  = tid >> 5;
    const int lane = tid & 31;
    const int bm = blockIdx.y * BM;
    const int bn = blockIdx.x * BN;
    const int warp_m = (wid >> 2) * 64;
    const int warp_n = (wid & 3) * 32;

    const __nv_bfloat16* gA[2] = { Ah + (size_t)bm * K, Al + (size_t)bm * K };
    const __nv_bfloat16* gB[2] = { Bh + (size_t)bn * K, Bl + (size_t)bn * K };

    float acc[4][4][4];
#pragma unroll
    for (int i = 0; i < 4; i++)
#pragma unroll
        for (int j = 0; j < 4; j++)
#pragma unroll
            for (int k = 0; k < 4; k++) acc[i][j][k] = 0.f;

    const int nchunk = K / BK;

    auto load_chunk = [&](int c) {
        const uint32_t bufb = smb + (c % STAGES) * STAGE_B;
        const int k0 = c * BK;
#pragma unroll
        for (int t = 0; t < 4; t++) {
            const __nv_bfloat16* src = (t < 2 ? gA[t] : gB[t - 2]) + k0;
            const uint32_t dstb = bufb + t * TILE_B;
#pragma unroll
            for (int i = 0; i < 2; i++) {
                const int idx = i * 256 + tid;
                const int row = idx >> 2, cc = idx & 3;
                const uint32_t sw = row * 64 + ((cc ^ ((row >> 1) & 3)) << 4);
                cp_async16(dstb + sw, src + (size_t)row * K + cc * 8);
            }
        }
        CP_COMMIT();
    };

    load_chunk(0);
    load_chunk(1);

    const int lrow  = lane & 15;
    const int lhalf = lane >> 4;

    for (int c = 0; c < nchunk; c++) {
        if (c + 2 < nchunk) { load_chunk(c + 2); CP_WAIT(2); }
        else if (c + 1 < nchunk) CP_WAIT(1);
        else                     CP_WAIT(0);
        __syncthreads();

        const uint32_t aHb = smb + (c % STAGES) * STAGE_B;
        const uint32_t aLb = aHb + TILE_B;
        const uint32_t bHb = aHb + 2 * TILE_B;
        const uint32_t bLb = aHb + 3 * TILE_B;

#pragma unroll
        for (int ks = 0; ks < 2; ks++) {
            const int ccol = ks * 2 + lhalf;
            uint32_t bh[2][4], bl[2][4];
#pragma unroll
            for (int j = 0; j < 2; j++) {
                const int row = warp_n + j * 16 + lrow;
                const uint32_t off = row * 64 + ((ccol ^ ((row >> 1) & 3)) << 4);
                ldm_x4(bh[j], bHb + off);
                ldm_x4(bl[j], bLb + off);
            }
#pragma unroll
            for (int mi = 0; mi < 4; mi++) {
                const int row = warp_m + mi * 16 + lrow;
                const uint32_t off = row * 64 + ((ccol ^ ((row >> 1) & 3)) << 4);
                uint32_t ah[4], al[4];
                ldm_x4(ah, aHb + off);
                ldm_x4(al, aLb + off);
#pragma unroll
                for (int nj = 0; nj < 4; nj++) {
                    const int p = nj >> 1, s = nj & 1;
                    mma_bf16(acc[mi][nj], ah, bh[p][s], bh[p][s + 2]);
                    mma_bf16(acc[mi][nj], ah, bl[p][s], bl[p][s + 2]);
                    mma_bf16(acc[mi][nj], al, bh[p][s], bh[p][s + 2]);
                }
            }
        }
        __syncthreads();
    }

    const int row_t = lane >> 2;
    const int col_t = (lane & 3) * 2;
#pragma unroll
    for (int mi = 0; mi < 4; mi++) {
#pragma unroll
        for (int r = 0; r < 2; r++) {
            const int row = bm + warp_m + mi * 16 + row_t + r * 8;
            float* crow = C + (size_t)row * N + bn;
#pragma unroll
            for (int nj = 0; nj < 4; nj++) {
                const int col = warp_n + nj * 8 + col_t;
                float2 v;
                v.x = acc[mi][nj][r * 2 + 0];
                v.y = acc[mi][nj][r * 2 + 1];
                if (bias) { v.x += bias[bn + col]; v.y += bias[bn + col + 1]; }
                *(float2*)(crow + col) = v;
            }
        }
    }
}

// ---------------------------------------------------------------------------
// fp32 -> bf16 hi/lo splits
// ---------------------------------------------------------------------------
__global__ __launch_bounds__(256) void split_rm(
    const float* __restrict__ in, __nv_bfloat16* __restrict__ hi,
    __nv_bfloat16* __restrict__ lo, int n4)
{
    int i = blockIdx.x * blockDim.x + threadIdx.x;
    if (i < n4) {
        float4 v = ((const float4*)in)[i];
        float f[4] = { v.x, v.y, v.z, v.w };
        __nv_bfloat16 h[4], l[4];
#pragma unroll
        for (int j = 0; j < 4; j++) {
            h[j] = __float2bfloat16_rn(f[j]);
            l[j] = __float2bfloat16_rn(f[j] - __bfloat162float(h[j]));
        }
        ((ushort4*)hi)[i] = make_ushort4(
            __bfloat16_as_ushort(h[0]), __bfloat16_as_ushort(h[1]),
            __bfloat16_as_ushort(h[2]), __bfloat16_as_ushort(h[3]));
        ((ushort4*)lo)[i] = make_ushort4(
            __bfloat16_as_ushort(l[0]), __bfloat16_as_ushort(l[1]),
            __bfloat16_as_ushort(l[2]), __bfloat16_as_ushort(l[3]));
    }
}

__global__ __launch_bounds__(256) void split_tr(
    const float* __restrict__ W, __nv_bfloat16* __restrict__ hi,
    __nv_bfloat16* __restrict__ lo, int K, int N)
{
    int idx = blockIdx.x * blockDim.x + threadIdx.x;
    if (idx < K * N) {
        int n = idx / K, k = idx % K;
        float v = W[(size_t)k * N + n];
        __nv_bfloat16 h = __float2bfloat16_rn(v);
        hi[idx] = h;
        lo[idx] = __float2bfloat16_rn(v - __bfloat162float(h));
    }
}

// ---------------------------------------------------------------------------
// Tensor-core windowed attention (flash-style, bf16x3, no online softmax).
// Block = one (b, window, head), 448 thr = 14 warps, warp w owns rows
// [16w,16w+16) of the 224-row padded window. K,V staged in smem as bf16
// hi/lo, [208 keys][64 dims], 128B rows, 16B-col XOR-(row&7) swizzle.
// Keys >=196 masked (p=0). Window-pad zero keys keep p=exp(0) per reference.
// Output written as bf16 hi/lo directly (feeds GEMM3).
// ---------------------------------------------------------------------------
#define AKEYS 208
#define ATHREADS 448
#define KV_PLANE (AKEYS * 128)        // 26624 B per plane
#define ATTN_SMEM (4 * KV_PLANE)      // 106496 B

__global__ __launch_bounds__(ATHREADS) void win_attn_mma(
    const float* __restrict__ qkv,
    __nv_bfloat16* __restrict__ ohi, __nv_bfloat16* __restrict__ olo)
{
    const int bidx = blockIdx.x;
    const int head = bidx % NHEAD;
    const int l    = (bidx / NHEAD) % (NWIN * NWIN);
    const int b    = bidx / (NHEAD * NWIN * NWIN);
    const int wi = l / NWIN, wj = l % NWIN;

    extern __shared__ char sm[];
    const uint32_t smb = smem_u32(sm);
    const uint32_t Khb = smb;
    const uint32_t Klb = smb + KV_PLANE;
    const uint32_t Vhb = smb + 2 * KV_PLANE;
    const uint32_t Vlb = smb + 3 * KV_PLANE;

    const int tid = threadIdx.x;

    // ---- stage K,V -> smem bf16 hi/lo, swizzled ----
    const int items = AKEYS * 8;                 // 8 chunks of 8 dims per key
    for (int i = tid; i < 2 * items; i += ATHREADS) {
        const int m  = (i >= items);             // 0: K, 1: V
        const int r  = (i % items) >> 3;
        const int ch = i & 7;
        float4 f0 = make_float4(0.f, 0.f, 0.f, 0.f);
        float4 f1 = make_float4(0.f, 0.f, 0.f, 0.f);
        if (r < NWP) {
            const int rr = r / WIN, rc = r % WIN;
            const int h = wi * WIN + rr, w = wj * WIN + rc;
            if (h < HIMG && w < WIMG) {
                const size_t base = (size_t)(b * NPOS + h * WIMG + w) * CQKV
                                    + (m ? 2 * CDIM : CDIM) + head * HD + ch * 8;
                f0 = *(const float4*)(qkv + base);
                f1 = *(const float4*)(qkv + base + 4);
            }
        }
        float f[8] = { f0.x, f0.y, f0.z, f0.w, f1.x, f1.y, f1.z, f1.w };
        uint32_t hp[4], lp[4];
#pragma unroll
        for (int j = 0; j < 4; j++) split2(f[2 * j], f[2 * j + 1], hp[j], lp[j]);
        const uint32_t off = r * 128 + ((ch ^ (r & 7)) << 4);
        const uint32_t hbase = (m ? Vhb : Khb) + off;
        const uint32_t lbase = (m ? Vlb : Klb) + off;
        asm volatile("st.shared.v4.b32 [%0], {%1,%2,%3,%4};"
                     :: "r"(hbase), "r"(hp[0]), "r"(hp[1]), "r"(hp[2]), "r"(hp[3]));
        asm volatile("st.shared.v4.b32 [%0], {%1,%2,%3,%4};"
                     :: "r"(lbase), "r"(lp[0]), "r"(lp[1]), "r"(lp[2]), "r"(lp[3]));
    }
    __syncthreads();

    const int lane = tid & 31;
    const int wid  = tid >> 5;
    const int rA = wid * 16 + (lane >> 2);   // row of c-frag regs 0,1
    const int rB = rA + 8;                   // row of c-frag regs 2,3
    const int kq = 2 * (lane & 3);

    // row -> global position (clamped; invalid rows discarded at store)
    auto rowpos = [&](int row, bool& valid, size_t& gpos) {
        const int rc = row < NWP ? row : 0;
        const int rr = rc / WIN, cc = rc % WIN;
        const int h = wi * WIN + rr, w = wj * WIN + cc;
        valid = (row < NWP) && (h < HIMG) && (w < WIMG);
        const int hc = h < HIMG ? h : 0, wc = w < WIMG ? w : 0;
        gpos = (size_t)(b * NPOS + hc * WIMG + wc);
    };
    bool vA, vB; size_t gA, gB;
    rowpos(rA, vA, gA);
    rowpos(rB, vB, gB);

    // ---- load Q fragments (hi/lo) directly from global fp32 ----
    uint32_t qh[4][4], ql[4][4];
    const size_t qbA = gA * CQKV + head * HD;
    const size_t qbB = gB * CQKV + head * HD;
#pragma unroll
    for (int ks = 0; ks < 4; ks++) {
        const int k0 = ks * 16 + kq;
        float2 a = *(const float2*)(qkv + qbA + k0);
        float2 bq = *(const float2*)(qkv + qbB + k0);
        float2 c = *(const float2*)(qkv + qbA + k0 + 8);
        float2 d = *(const float2*)(qkv + qbB + k0 + 8);
        split2(a.x, a.y, qh[ks][0], ql[ks][0]);
        split2(bq.x, bq.y, qh[ks][1], ql[ks][1]);
        split2(c.x, c.y, qh[ks][2], ql[ks][2]);
        split2(d.x, d.y, qh[ks][3], ql[ks][3]);
    }

    float Oacc[8][4];
#pragma unroll
    for (int t = 0; t < 8; t++)
#pragma unroll
        for (int c = 0; c < 4; c++) Oacc[t][c] = 0.f;
    float lsA = 0.f, lsB = 0.f;

    const int lrow  = lane & 15;
    const int lhalf = lane >> 4;

    for (int kt = 0; kt < AKEYS / 16; kt++) {     // 13 key tiles
        const int krow = kt * 16 + lrow;
        float sacc[2][4];
#pragma unroll
        for (int s = 0; s < 2; s++)
#pragma unroll
            for (int c = 0; c < 4; c++) sacc[s][c] = 0.f;

        // ---- S = Q K^T (bf16x3) ----
#pragma unroll
        for (int ks = 0; ks < 4; ks++) {
            const uint32_t off = krow * 128 + (((ks * 2 + lhalf) ^ (krow & 7)) << 4);
            uint32_t kh[4], kl[4];
            ldm_x4(kh, Khb + off);
            ldm_x4(kl, Klb + off);
#pragma unroll
            for (int s = 0; s < 2; s++) {
                mma_bf16(sacc[s], qh[ks], kh[s], kh[s + 2]);
                mma_bf16(sacc[s], qh[ks], kl[s], kl[s + 2]);
                mma_bf16(sacc[s], ql[ks], kh[s], kh[s + 2]);
            }
        }

        // ---- exp + mask + pack P fragments ----
        float p[2][4];
#pragma unroll
        for (int s = 0; s < 2; s++)
#pragma unroll
            for (int c = 0; c < 4; c++) {
                const int col = kt * 16 + s * 8 + kq + (c & 1);
                p[s][c] = (col < NWP) ? __expf(sacc[s][c] * 0.125f) : 0.f;
            }
        lsA += p[0][0] + p[0][1] + p[1][0] + p[1][1];
        lsB += p[0][2] + p[0][3] + p[1][2] + p[1][3];
        uint32_t ph[4], pl[4];
        split2(p[0][0], p[0][1], ph[0], pl[0]);
        split2(p[0][2], p[0][3], ph[1], pl[1]);
        split2(p[1][0], p[1][1], ph[2], pl[2]);
        split2(p[1][2], p[1][3], ph[3], pl[3]);

        // ---- O += P V (bf16x3), V via ldmatrix.trans ----
#pragma unroll
        for (int g = 0; g < 4; g++) {
            const uint32_t voff = krow * 128 + (((g * 2 + lhalf) ^ (krow & 7)) << 4);
            uint32_t vh[4], vl[4];
            ldm_x4_trans(vh, Vhb + voff);
            ldm_x4_trans(vl, Vlb + voff);
            mma_bf16(Oacc[2 * g],     ph, vh[0], vh[1]);
            mma_bf16(Oacc[2 * g],     ph, vl[0], vl[1]);
            mma_bf16(Oacc[2 * g],     pl, vh[0], vh[1]);
            mma_bf16(Oacc[2 * g + 1], ph, vh[2], vh[3]);
            mma_bf16(Oacc[2 * g + 1], ph, vl[2], vl[3]);
            mma_bf16(Oacc[2 * g + 1], pl, vh[2], vh[3]);
        }
    }

    // ---- normalize + store ----
    lsA += __shfl_xor_sync(0xffffffffu, lsA, 1);
    lsA += __shfl_xor_sync(0xffffffffu, lsA, 2);
    lsB += __shfl_xor_sync(0xffffffffu, lsB, 1);
    lsB += __shfl_xor_sync(0xffffffffu, lsB, 2);
    const float invA = 1.f / lsA;
    const float invB = 1.f / lsB;

    if (vA) {
        const size_t obase = gA * CDIM + head * HD + kq;
#pragma unroll
        for (int t = 0; t < 8; t++) {
            uint32_t hp, lp;
            split2(Oacc[t][0] * invA, Oacc[t][1] * invA, hp, lp);
            *(uint32_t*)(ohi + obase + t * 8) = hp;
            *(uint32_t*)(olo + obase + t * 8) = lp;
        }
    }
    if (vB) {
        const size_t obase = gB * CDIM + head * HD + kq;
#pragma unroll
        for (int t = 0; t < 8; t++) {
            uint32_t hp, lp;
            split2(Oacc[t][2] * invB, Oacc[t][3] * invB, hp, lp);
            *(uint32_t*)(ohi + obase + t * 8) = hp;
            *(uint32_t*)(olo + obase + t * 8) = lp;
        }
    }
}

// ---------------------------------------------------------------------------
extern "C" void kernel_launch(void* const* d_in, const int* in_sizes, int n_in,
                              void* d_out, int out_size)
{
    const float* x     = (const float*)d_in[0];
    const float* Wqkv  = (const float*)d_in[1];
    const float* Wproj = (const float*)d_in[2];
    const float* bproj = (const float*)d_in[3];
    float* out = (float*)d_out;

    float *qkv;
    __nv_bfloat16 *ahi, *alo, *bhi, *blo;
    cudaGetSymbolAddress((void**)&qkv, g_qkv);
    cudaGetSymbolAddress((void**)&ahi, g_ahi);
    cudaGetSymbolAddress((void**)&alo, g_alo);
    cudaGetSymbolAddress((void**)&bhi, g_bhi);
    cudaGetSymbolAddress((void**)&blo, g_blo);

    cudaFuncSetAttribute(gemm_mma_bf16x3,
                         cudaFuncAttributeMaxDynamicSharedMemorySize, GEMM_SMEM);
    cudaFuncSetAttribute(win_attn_mma,
                         cudaFuncAttributeMaxDynamicSharedMemorySize, ATTN_SMEM);

    const int M = MROWS;

    // ---- GEMM1: qkv = x @ Wqkv ----
    {
        int n4 = M * CDIM / 4;
        split_rm<<<(n4 + 255) / 256, 256>>>(x, ahi, alo, n4);
        int ne = CDIM * CQKV;
        split_tr<<<(ne + 255) / 256, 256>>>(Wqkv, bhi, blo, CDIM, CQKV);
        dim3 grid(CQKV / BN, M / BM);
        gemm_mma_bf16x3<<<grid, 256, GEMM_SMEM>>>(
            ahi, alo, bhi, blo, nullptr, qkv, M, CQKV, CDIM);
    }

    // ---- windowed attention (tensor cores, writes bf16 hi/lo) ----
    {
        dim3 grid(BATCH * NWIN * NWIN * NHEAD);
        win_attn_mma<<<grid, ATHREADS, ATTN_SMEM>>>(qkv, ahi, alo);
    }

    // ---- GEMM3: out = att @ Wproj + bproj ----
    {
        int ne = CDIM * CDIM;
        split_tr<<<(ne + 255) / 256, 256>>>(Wproj, bhi, blo, CDIM, CDIM);
        dim3 grid(CDIM / BN, M / BM);
        gemm_mma_bf16x3<<<grid, 256, GEMM_SMEM>>>(
            ahi, alo, bhi, blo, bproj, out, M, CDIM, CDIM);
    }
}

// round 17
// speedup vs baseline: 2.1453x; 1.3158x over previous
#include <cuda_runtime.h>
#include <cuda_bf16.h>
#include <cstdint>

#define BATCH 8
#define HIMG 80
#define WIMG 80
#define CDIM 768
#define NPOS (HIMG * WIMG)        // 6400
#define CQKV (3 * CDIM)           // 2304
#define WIN 14
#define NWIN 6
#define NHEAD 12
#define HD 64
#define NWP (WIN * WIN)           // 196
#define MROWS (BATCH * NPOS)      // 51200

// ---------------- scratch (__device__ globals: allocation-free rule) -------
__device__ float g_qkv[(size_t)MROWS * CQKV];
__device__ float g_xt [(size_t)MROWS * CDIM];     // tf32-rounded x
__device__ float g_bt [(size_t)CQKV * CDIM];      // tf32-rounded Wqkv^T
__device__ __nv_bfloat16 g_ahi[(size_t)MROWS * CDIM];
__device__ __nv_bfloat16 g_alo[(size_t)MROWS * CDIM];
__device__ __nv_bfloat16 g_bhi[(size_t)CQKV * CDIM];
__device__ __nv_bfloat16 g_blo[(size_t)CQKV * CDIM];

// ---------------- PTX helpers (no 'a'-suffix features) ---------------------
__device__ __forceinline__ uint32_t smem_u32(const void* p) {
    uint32_t a;
    asm("{ .reg .u64 t; cvta.to.shared.u64 t, %1; cvt.u32.u64 %0, t; }"
        : "=r"(a) : "l"(p));
    return a;
}
__device__ __forceinline__ void cp_async16(uint32_t dst, const void* src) {
    asm volatile("cp.async.cg.shared.global [%0], [%1], 16;"
                 :: "r"(dst), "l"(src));
}
#define CP_COMMIT() asm volatile("cp.async.commit_group;" ::: "memory")
#define CP_WAIT(n)  asm volatile("cp.async.wait_group %0;" :: "n"(n) : "memory")

__device__ __forceinline__ void ldm_x4(uint32_t* r, uint32_t addr) {
    asm volatile("ldmatrix.sync.aligned.m8n8.x4.shared.b16 {%0,%1,%2,%3}, [%4];"
                 : "=r"(r[0]), "=r"(r[1]), "=r"(r[2]), "=r"(r[3]) : "r"(addr));
}
__device__ __forceinline__ void ldm_x4_trans(uint32_t* r, uint32_t addr) {
    asm volatile("ldmatrix.sync.aligned.m8n8.x4.trans.shared.b16 {%0,%1,%2,%3}, [%4];"
                 : "=r"(r[0]), "=r"(r[1]), "=r"(r[2]), "=r"(r[3]) : "r"(addr));
}
__device__ __forceinline__ void mma_bf16(float* d, const uint32_t* a,
                                         uint32_t b0, uint32_t b1) {
    asm volatile(
        "mma.sync.aligned.m16n8k16.row.col.f32.bf16.bf16.f32 "
        "{%0,%1,%2,%3}, {%4,%5,%6,%7}, {%8,%9}, {%0,%1,%2,%3};"
        : "+f"(d[0]), "+f"(d[1]), "+f"(d[2]), "+f"(d[3])
        : "r"(a[0]), "r"(a[1]), "r"(a[2]), "r"(a[3]), "r"(b0), "r"(b1));
}
__device__ __forceinline__ void mma_tf32(float* d, const uint32_t* a,
                                         uint32_t b0, uint32_t b1) {
    asm volatile(
        "mma.sync.aligned.m16n8k8.row.col.f32.tf32.tf32.f32 "
        "{%0,%1,%2,%3}, {%4,%5,%6,%7}, {%8,%9}, {%0,%1,%2,%3};"
        : "+f"(d[0]), "+f"(d[1]), "+f"(d[2]), "+f"(d[3])
        : "r"(a[0]), "r"(a[1]), "r"(a[2]), "r"(a[3]), "r"(b0), "r"(b1));
}
__device__ __forceinline__ uint32_t to_tf32(float x) {
    uint32_t r;
    asm("cvt.rna.tf32.f32 %0, %1;" : "=r"(r) : "f"(x));
    return r;
}
// split two fp32 into packed bf16 hi and lo pairs
__device__ __forceinline__ void split2(float x, float y,
                                       uint32_t& hp, uint32_t& lp) {
    __nv_bfloat16 hx = __float2bfloat16_rn(x);
    __nv_bfloat16 hy = __float2bfloat16_rn(y);
    __nv_bfloat16 lx = __float2bfloat16_rn(x - __bfloat162float(hx));
    __nv_bfloat16 ly = __float2bfloat16_rn(y - __bfloat162float(hy));
    hp = (uint32_t)__bfloat16_as_ushort(hx) |
         ((uint32_t)__bfloat16_as_ushort(hy) << 16);
    lp = (uint32_t)__bfloat16_as_ushort(lx) |
         ((uint32_t)__bfloat16_as_ushort(ly) << 16);
}

// ---------------------------------------------------------------------------
// tf32 GEMM via mma.sync m16n8k8: C = A*B, fp32 acc. A[M,K] fp32 (tf32-
// rounded), B[N,K] fp32 (tf32-rounded). 128x128 tile, BK=32, 3-stage ring,
// 256 thr, 2 CTA/SM. smem rows 128B (8 x 16B chunks), swizzle ch ^ (row&7).
// ---------------------------------------------------------------------------
#define TBM 128
#define TBN 128
#define TBK 32
#define T_TILE (TBM * TBK * 4)          // 16384
#define T_STAGE (2 * T_TILE)            // 32768
#define TGEMM_SMEM (3 * T_STAGE)        // 98304

__global__ __launch_bounds__(256, 2) void gemm_tf32(
    const float* __restrict__ A, const float* __restrict__ B,
    const float* __restrict__ bias, float* __restrict__ C,
    int M, int N, int K)
{
    extern __shared__ char sm[];
    const uint32_t smb = smem_u32(sm);
    const int tid  = threadIdx.x;
    const int wid  = tid >> 5;
    const int lane = tid & 31;
    const int bm = blockIdx.y * TBM;
    const int bn = blockIdx.x * TBN;
    const int warp_m = (wid >> 2) * 64;
    const int warp_n = (wid & 3) * 32;

    const float* gA = A + (size_t)bm * K;
    const float* gB = B + (size_t)bn * K;

    float acc[4][4][4];
#pragma unroll
    for (int i = 0; i < 4; i++)
#pragma unroll
        for (int j = 0; j < 4; j++)
#pragma unroll
            for (int k = 0; k < 4; k++) acc[i][j][k] = 0.f;

    const int nchunk = K / TBK;    // 24

    auto load_chunk = [&](int c) {
        const uint32_t bufb = smb + (c % 3) * T_STAGE;
        const int k0 = c * TBK;
#pragma unroll
        for (int t = 0; t < 2; t++) {
            const float* src = (t == 0 ? gA : gB) + k0;
            const uint32_t dstb = bufb + t * T_TILE;
#pragma unroll
            for (int i = 0; i < 4; i++) {
                const int idx = i * 256 + tid;            // 0..1023
                const int row = idx >> 3, cc = idx & 7;   // 8 x 16B per row
                const uint32_t sw = row * 128 + ((cc ^ (row & 7)) << 4);
                cp_async16(dstb + sw, src + (size_t)row * K + cc * 4);
            }
        }
        CP_COMMIT();
    };

    load_chunk(0);
    load_chunk(1);

    const int g    = lane >> 3;   // ldmatrix tile group 0..3
    const int trow = lane & 7;

    for (int c = 0; c < nchunk; c++) {
        if (c + 2 < nchunk) { load_chunk(c + 2); CP_WAIT(2); }
        else if (c + 1 < nchunk) CP_WAIT(1);
        else                     CP_WAIT(0);
        __syncthreads();

        const uint32_t Ab = smb + (c % 3) * T_STAGE;
        const uint32_t Bb = Ab + T_TILE;

#pragma unroll
        for (int ks = 0; ks < 4; ks++) {       // K8 steps
            // B fragments: tiles (g>>1 -> row block, g&1 -> k chunk)
            uint32_t bfr[2][4];
#pragma unroll
            for (int jp = 0; jp < 2; jp++) {
                const int row = warp_n + jp * 16 + ((g >> 1) << 3) + trow;
                const int ch  = 2 * ks + (g & 1);
                ldm_x4(bfr[jp], Bb + row * 128 + ((ch ^ (row & 7)) << 4));
            }
#pragma unroll
            for (int mi = 0; mi < 4; mi++) {
                // A fragment: tiles (g&1 -> row block, g>>1 -> k chunk)
                const int row = warp_m + mi * 16 + ((g & 1) << 3) + trow;
                const int ch  = 2 * ks + (g >> 1);
                uint32_t a[4];
                ldm_x4(a, Ab + row * 128 + ((ch ^ (row & 7)) << 4));
                mma_tf32(acc[mi][0], a, bfr[0][0], bfr[0][1]);
                mma_tf32(acc[mi][1], a, bfr[0][2], bfr[0][3]);
                mma_tf32(acc[mi][2], a, bfr[1][0], bfr[1][1]);
                mma_tf32(acc[mi][3], a, bfr[1][2], bfr[1][3]);
            }
        }
        __syncthreads();
    }

    const int row_t = lane >> 2;
    const int col_t = (lane & 3) * 2;
#pragma unroll
    for (int mi = 0; mi < 4; mi++) {
#pragma unroll
        for (int r = 0; r < 2; r++) {
            const int row = bm + warp_m + mi * 16 + row_t + r * 8;
            float* crow = C + (size_t)row * N + bn;
#pragma unroll
            for (int nj = 0; nj < 4; nj++) {
                const int col = warp_n + nj * 8 + col_t;
                float2 v;
                v.x = acc[mi][nj][r * 2 + 0];
                v.y = acc[mi][nj][r * 2 + 1];
                if (bias) { v.x += bias[bn + col]; v.y += bias[bn + col + 1]; }
                *(float2*)(crow + col) = v;
            }
        }
    }
}

// ---------------------------------------------------------------------------
// bf16x3 GEMM via mma.sync (measured-best config; used for GEMM3).
// ---------------------------------------------------------------------------
#define BM 128
#define BN 128
#define BK 32
#define STAGES 3
#define TILE_B (BM * BK * 2)          // 8192
#define STAGE_B (4 * TILE_B)          // 32768
#define GEMM_SMEM (STAGES * STAGE_B)  // 98304

__global__ __launch_bounds__(256, 2) void gemm_mma_bf16x3(
    const __nv_bfloat16* __restrict__ Ah, const __nv_bfloat16* __restrict__ Al,
    const __nv_bfloat16* __restrict__ Bh, const __nv_bfloat16* __restrict__ Bl,
    const float* __restrict__ bias, float* __restrict__ C,
    int M, int N, int K)
{
    extern __shared__ char sm[];
    const uint32_t smb = smem_u32(sm);
    const int tid  = threadIdx.x;
    const int wid  = tid >> 5;
    const int lane = tid & 31;
    const int bm = blockIdx.y * BM;
    const int bn = blockIdx.x * BN;
    const int warp_m = (wid >> 2) * 64;
    const int warp_n = (wid & 3) * 32;

    const __nv_bfloat16* gA[2] = { Ah + (size_t)bm * K, Al + (size_t)bm * K };
    const __nv_bfloat16* gB[2] = { Bh + (size_t)bn * K, Bl + (size_t)bn * K };

    float acc[4][4][4];
#pragma unroll
    for (int i = 0; i < 4; i++)
#pragma unroll
        for (int j = 0; j < 4; j++)
#pragma unroll
            for (int k = 0; k < 4; k++) acc[i][j][k] = 0.f;

    const int nchunk = K / BK;

    auto load_chunk = [&](int c) {
        const uint32_t bufb = smb + (c % STAGES) * STAGE_B;
        const int k0 = c * BK;
#pragma unroll
        for (int t = 0; t < 4; t++) {
            const __nv_bfloat16* src = (t < 2 ? gA[t] : gB[t - 2]) + k0;
            const uint32_t dstb = bufb + t * TILE_B;
#pragma unroll
            for (int i = 0; i < 2; i++) {
                const int idx = i * 256 + tid;
                const int row = idx >> 2, cc = idx & 3;
                const uint32_t sw = row * 64 + ((cc ^ ((row >> 1) & 3)) << 4);
                cp_async16(dstb + sw, src + (size_t)row * K + cc * 8);
            }
        }
        CP_COMMIT();
    };

    load_chunk(0);
    load_chunk(1);

    const int lrow  = lane & 15;
    const int lhalf = lane >> 4;

    for (int c = 0; c < nchunk; c++) {
        if (c + 2 < nchunk) { load_chunk(c + 2); CP_WAIT(2); }
        else if (c + 1 < nchunk) CP_WAIT(1);
        else                     CP_WAIT(0);
        __syncthreads();

        const uint32_t aHb = smb + (c % STAGES) * STAGE_B;
        const uint32_t aLb = aHb + TILE_B;
        const uint32_t bHb = aHb + 2 * TILE_B;
        const uint32_t bLb = aHb + 3 * TILE_B;

#pragma unroll
        for (int ks = 0; ks < 2; ks++) {
            const int ccol = ks * 2 + lhalf;
            uint32_t bh[2][4], bl[2][4];
#pragma unroll
            for (int j = 0; j < 2; j++) {
                const int row = warp_n + j * 16 + lrow;
                const uint32_t off = row * 64 + ((ccol ^ ((row >> 1) & 3)) << 4);
                ldm_x4(bh[j], bHb + off);
                ldm_x4(bl[j], bLb + off);
            }
#pragma unroll
            for (int mi = 0; mi < 4; mi++) {
                const int row = warp_m + mi * 16 + lrow;
                const uint32_t off = row * 64 + ((ccol ^ ((row >> 1) & 3)) << 4);
                uint32_t ah[4], al[4];
                ldm_x4(ah, aHb + off);
                ldm_x4(al, aLb + off);
#pragma unroll
                for (int nj = 0; nj < 4; nj++) {
                    const int p = nj >> 1, s = nj & 1;
                    mma_bf16(acc[mi][nj], ah, bh[p][s], bh[p][s + 2]);
                    mma_bf16(acc[mi][nj], ah, bl[p][s], bl[p][s + 2]);
                    mma_bf16(acc[mi][nj], al, bh[p][s], bh[p][s + 2]);
                }
            }
        }
        __syncthreads();
    }

    const int row_t = lane >> 2;
    const int col_t = (lane & 3) * 2;
#pragma unroll
    for (int mi = 0; mi < 4; mi++) {
#pragma unroll
        for (int r = 0; r < 2; r++) {
            const int row = bm + warp_m + mi * 16 + row_t + r * 8;
            float* crow = C + (size_t)row * N + bn;
#pragma unroll
            for (int nj = 0; nj < 4; nj++) {
                const int col = warp_n + nj * 8 + col_t;
                float2 v;
                v.x = acc[mi][nj][r * 2 + 0];
                v.y = acc[mi][nj][r * 2 + 1];
                if (bias) { v.x += bias[bn + col]; v.y += bias[bn + col + 1]; }
                *(float2*)(crow + col) = v;
            }
        }
    }
}

// ---------------------------------------------------------------------------
// prep kernels
// ---------------------------------------------------------------------------
// fp32 -> tf32-rounded fp32 (row-major copy)
__global__ __launch_bounds__(256) void prep_tf32(
    const float* __restrict__ in, float* __restrict__ out, int n4)
{
    int i = blockIdx.x * blockDim.x + threadIdx.x;
    if (i < n4) {
        float4 v = ((const float4*)in)[i];
        uint4 o;
        o.x = to_tf32(v.x); o.y = to_tf32(v.y);
        o.z = to_tf32(v.z); o.w = to_tf32(v.w);
        ((uint4*)out)[i] = o;
    }
}

// fp32 W[K,N] -> tf32-rounded fp32 W^T[N,K]
__global__ __launch_bounds__(256) void tr_tf32(
    const float* __restrict__ W, float* __restrict__ Wt, int K, int N)
{
    int idx = blockIdx.x * blockDim.x + threadIdx.x;
    if (idx < K * N) {
        int n = idx / K, k = idx % K;
        uint32_t r = to_tf32(W[(size_t)k * N + n]);
        ((uint32_t*)Wt)[idx] = r;
    }
}

// fp32 W[K,N] -> transposed bf16 hi/lo [N,K]
__global__ __launch_bounds__(256) void split_tr(
    const float* __restrict__ W, __nv_bfloat16* __restrict__ hi,
    __nv_bfloat16* __restrict__ lo, int K, int N)
{
    int idx = blockIdx.x * blockDim.x + threadIdx.x;
    if (idx < K * N) {
        int n = idx / K, k = idx % K;
        float v = W[(size_t)k * N + n];
        __nv_bfloat16 h = __float2bfloat16_rn(v);
        hi[idx] = h;
        lo[idx] = __float2bfloat16_rn(v - __bfloat162float(h));
    }
}

// ---------------------------------------------------------------------------
// Tensor-core windowed attention (flash-style, bf16x3, no online softmax).
// Unchanged from R15 (measured 548us).
// ---------------------------------------------------------------------------
#define AKEYS 208
#define ATHREADS 448
#define KV_PLANE (AKEYS * 128)        // 26624 B per plane
#define ATTN_SMEM (4 * KV_PLANE)      // 106496 B

__global__ __launch_bounds__(ATHREADS) void win_attn_mma(
    const float* __restrict__ qkv,
    __nv_bfloat16* __restrict__ ohi, __nv_bfloat16* __restrict__ olo)
{
    const int bidx = blockIdx.x;
    const int head = bidx % NHEAD;
    const int l    = (bidx / NHEAD) % (NWIN * NWIN);
    const int b    = bidx / (NHEAD * NWIN * NWIN);
    const int wi = l / NWIN, wj = l % NWIN;

    extern __shared__ char sm[];
    const uint32_t smb = smem_u32(sm);
    const uint32_t Khb = smb;
    const uint32_t Klb = smb + KV_PLANE;
    const uint32_t Vhb = smb + 2 * KV_PLANE;
    const uint32_t Vlb = smb + 3 * KV_PLANE;

    const int tid = threadIdx.x;

    const int items = AKEYS * 8;
    for (int i = tid; i < 2 * items; i += ATHREADS) {
        const int m  = (i >= items);
        const int r  = (i % items) >> 3;
        const int ch = i & 7;
        float4 f0 = make_float4(0.f, 0.f, 0.f, 0.f);
        float4 f1 = make_float4(0.f, 0.f, 0.f, 0.f);
        if (r < NWP) {
            const int rr = r / WIN, rc = r % WIN;
            const int h = wi * WIN + rr, w = wj * WIN + rc;
            if (h < HIMG && w < WIMG) {
                const size_t base = (size_t)(b * NPOS + h * WIMG + w) * CQKV
                                    + (m ? 2 * CDIM : CDIM) + head * HD + ch * 8;
                f0 = *(const float4*)(qkv + base);
                f1 = *(const float4*)(qkv + base + 4);
            }
        }
        float f[8] = { f0.x, f0.y, f0.z, f0.w, f1.x, f1.y, f1.z, f1.w };
        uint32_t hp[4], lp[4];
#pragma unroll
        for (int j = 0; j < 4; j++) split2(f[2 * j], f[2 * j + 1], hp[j], lp[j]);
        const uint32_t off = r * 128 + ((ch ^ (r & 7)) << 4);
        const uint32_t hbase = (m ? Vhb : Khb) + off;
        const uint32_t lbase = (m ? Vlb : Klb) + off;
        asm volatile("st.shared.v4.b32 [%0], {%1,%2,%3,%4};"
                     :: "r"(hbase), "r"(hp[0]), "r"(hp[1]), "r"(hp[2]), "r"(hp[3]));
        asm volatile("st.shared.v4.b32 [%0], {%1,%2,%3,%4};"
                     :: "r"(lbase), "r"(lp[0]), "r"(lp[1]), "r"(lp[2]), "r"(lp[3]));
    }
    __syncthreads();

    const int lane = tid & 31;
    const int wid  = tid >> 5;
    const int rA = wid * 16 + (lane >> 2);
    const int rB = rA + 8;
    const int kq = 2 * (lane & 3);

    auto rowpos = [&](int row, bool& valid, size_t& gpos) {
        const int rc = row < NWP ? row : 0;
        const int rr = rc / WIN, cc = rc % WIN;
        const int h = wi * WIN + rr, w = wj * WIN + cc;
        valid = (row < NWP) && (h < HIMG) && (w < WIMG);
        const int hc = h < HIMG ? h : 0, wc = w < WIMG ? w : 0;
        gpos = (size_t)(b * NPOS + hc * WIMG + wc);
    };
    bool vA, vB; size_t gA, gB;
    rowpos(rA, vA, gA);
    rowpos(rB, vB, gB);

    uint32_t qh[4][4], ql[4][4];
    const size_t qbA = gA * CQKV + head * HD;
    const size_t qbB = gB * CQKV + head * HD;
#pragma unroll
    for (int ks = 0; ks < 4; ks++) {
        const int k0 = ks * 16 + kq;
        float2 a = *(const float2*)(qkv + qbA + k0);
        float2 bq = *(const float2*)(qkv + qbB + k0);
        float2 c = *(const float2*)(qkv + qbA + k0 + 8);
        float2 d = *(const float2*)(qkv + qbB + k0 + 8);
        split2(a.x, a.y, qh[ks][0], ql[ks][0]);
        split2(bq.x, bq.y, qh[ks][1], ql[ks][1]);
        split2(c.x, c.y, qh[ks][2], ql[ks][2]);
        split2(d.x, d.y, qh[ks][3], ql[ks][3]);
    }

    float Oacc[8][4];
#pragma unroll
    for (int t = 0; t < 8; t++)
#pragma unroll
        for (int c = 0; c < 4; c++) Oacc[t][c] = 0.f;
    float lsA = 0.f, lsB = 0.f;

    const int lrow  = lane & 15;
    const int lhalf = lane >> 4;

    for (int kt = 0; kt < AKEYS / 16; kt++) {
        const int krow = kt * 16 + lrow;
        float sacc[2][4];
#pragma unroll
        for (int s = 0; s < 2; s++)
#pragma unroll
            for (int c = 0; c < 4; c++) sacc[s][c] = 0.f;

#pragma unroll
        for (int ks = 0; ks < 4; ks++) {
            const uint32_t off = krow * 128 + (((ks * 2 + lhalf) ^ (krow & 7)) << 4);
            uint32_t kh[4], kl[4];
            ldm_x4(kh, Khb + off);
            ldm_x4(kl, Klb + off);
#pragma unroll
            for (int s = 0; s < 2; s++) {
                mma_bf16(sacc[s], qh[ks], kh[s], kh[s + 2]);
                mma_bf16(sacc[s], qh[ks], kl[s], kl[s + 2]);
                mma_bf16(sacc[s], ql[ks], kh[s], kh[s + 2]);
            }
        }

        float p[2][4];
#pragma unroll
        for (int s = 0; s < 2; s++)
#pragma unroll
            for (int c = 0; c < 4; c++) {
                const int col = kt * 16 + s * 8 + kq + (c & 1);
                p[s][c] = (col < NWP) ? __expf(sacc[s][c] * 0.125f) : 0.f;
            }
        lsA += p[0][0] + p[0][1] + p[1][0] + p[1][1];
        lsB += p[0][2] + p[0][3] + p[1][2] + p[1][3];
        uint32_t ph[4], pl[4];
        split2(p[0][0], p[0][1], ph[0], pl[0]);
        split2(p[0][2], p[0][3], ph[1], pl[1]);
        split2(p[1][0], p[1][1], ph[2], pl[2]);
        split2(p[1][2], p[1][3], ph[3], pl[3]);

#pragma unroll
        for (int g = 0; g < 4; g++) {
            const uint32_t voff = krow * 128 + (((g * 2 + lhalf) ^ (krow & 7)) << 4);
            uint32_t vh[4], vl[4];
            ldm_x4_trans(vh, Vhb + voff);
            ldm_x4_trans(vl, Vlb + voff);
            mma_bf16(Oacc[2 * g],     ph, vh[0], vh[1]);
            mma_bf16(Oacc[2 * g],     ph, vl[0], vl[1]);
            mma_bf16(Oacc[2 * g],     pl, vh[0], vh[1]);
            mma_bf16(Oacc[2 * g + 1], ph, vh[2], vh[3]);
            mma_bf16(Oacc[2 * g + 1], ph, vl[2], vl[3]);
            mma_bf16(Oacc[2 * g + 1], pl, vh[2], vh[3]);
        }
    }

    lsA += __shfl_xor_sync(0xffffffffu, lsA, 1);
    lsA += __shfl_xor_sync(0xffffffffu, lsA, 2);
    lsB += __shfl_xor_sync(0xffffffffu, lsB, 1);
    lsB += __shfl_xor_sync(0xffffffffu, lsB, 2);
    const float invA = 1.f / lsA;
    const float invB = 1.f / lsB;

    if (vA) {
        const size_t obase = gA * CDIM + head * HD + kq;
#pragma unroll
        for (int t = 0; t < 8; t++) {
            uint32_t hp, lp;
            split2(Oacc[t][0] * invA, Oacc[t][1] * invA, hp, lp);
            *(uint32_t*)(ohi + obase + t * 8) = hp;
            *(uint32_t*)(olo + obase + t * 8) = lp;
        }
    }
    if (vB) {
        const size_t obase = gB * CDIM + head * HD + kq;
#pragma unroll
        for (int t = 0; t < 8; t++) {
            uint32_t hp, lp;
            split2(Oacc[t][2] * invB, Oacc[t][3] * invB, hp, lp);
            *(uint32_t*)(ohi + obase + t * 8) = hp;
            *(uint32_t*)(olo + obase + t * 8) = lp;
        }
    }
}

// ---------------------------------------------------------------------------
extern "C" void kernel_launch(void* const* d_in, const int* in_sizes, int n_in,
                              void* d_out, int out_size)
{
    const float* x     = (const float*)d_in[0];
    const float* Wqkv  = (const float*)d_in[1];
    const float* Wproj = (const float*)d_in[2];
    const float* bproj = (const float*)d_in[3];
    float* out = (float*)d_out;

    float *qkv, *xt, *bt;
    __nv_bfloat16 *ahi, *alo, *bhi, *blo;
    cudaGetSymbolAddress((void**)&qkv, g_qkv);
    cudaGetSymbolAddress((void**)&xt,  g_xt);
    cudaGetSymbolAddress((void**)&bt,  g_bt);
    cudaGetSymbolAddress((void**)&ahi, g_ahi);
    cudaGetSymbolAddress((void**)&alo, g_alo);
    cudaGetSymbolAddress((void**)&bhi, g_bhi);
    cudaGetSymbolAddress((void**)&blo, g_blo);

    cudaFuncSetAttribute(gemm_tf32,
                         cudaFuncAttributeMaxDynamicSharedMemorySize, TGEMM_SMEM);
    cudaFuncSetAttribute(gemm_mma_bf16x3,
                         cudaFuncAttributeMaxDynamicSharedMemorySize, GEMM_SMEM);
    cudaFuncSetAttribute(win_attn_mma,
                         cudaFuncAttributeMaxDynamicSharedMemorySize, ATTN_SMEM);

    const int M = MROWS;

    // ---- GEMM1 (tf32): qkv = x @ Wqkv ----
    {
        int n4 = M * CDIM / 4;
        prep_tf32<<<(n4 + 255) / 256, 256>>>(x, xt, n4);
        int ne = CDIM * CQKV;
        tr_tf32<<<(ne + 255) / 256, 256>>>(Wqkv, bt, CDIM, CQKV);
        dim3 grid(CQKV / TBN, M / TBM);
        gemm_tf32<<<grid, 256, TGEMM_SMEM>>>(xt, bt, nullptr, qkv, M, CQKV, CDIM);
    }

    // ---- windowed attention (tensor cores, writes bf16 hi/lo) ----
    {
        dim3 grid(BATCH * NWIN * NWIN * NHEAD);
        win_attn_mma<<<grid, ATHREADS, ATTN_SMEM>>>(qkv, ahi, alo);
    }

    // ---- GEMM3 (bf16x3): out = att @ Wproj + bproj ----
    {
        int ne = CDIM * CDIM;
        split_tr<<<(ne + 255) / 256, 256>>>(Wproj, bhi, blo, CDIM, CDIM);
        dim3 grid(CDIM / BN, M / BM);
        gemm_mma_bf16x3<<<grid, 256, GEMM_SMEM>>>(
            ahi, alo, bhi, blo, bproj, out, M, CDIM, CDIM);
    }
}